// round 1
// baseline (speedup 1.0000x reference)
#include <cuda_runtime.h>
#include <cstdint>

// ---------------- problem constants ----------------
#define BATCH   4
#define HH      64
#define WW      64
#define CMODEL  256
#define NHEADS  8
#define NK      4
#define NSCALES 4
#define DK      32            // CMODEL / NHEADS
#define NPIX    (HH*WW)       // 4096
#define NROWS   (BATCH*NPIX)  // 16384

// key pyramid: 16,32,64,128 ; rows per scale = B*h*w
// row offsets into projected-key buffer
// 0, 1024, 5120, 21504 ; total 87040
#define KF_ROWS 87040

// ---------------- scratch (device globals; allocation-free) ----------------
__device__ float g_q   [(size_t)NROWS * CMODEL];      // 16 MB
__device__ float g_off [(size_t)NROWS * CMODEL];      // 16 MB
__device__ float g_attn[(size_t)NROWS * 128];         // 8 MB
__device__ float g_kf  [(size_t)KF_ROWS * CMODEL];    // 89 MB
__device__ float g_feat[(size_t)NROWS * CMODEL];      // 16 MB

// ---------------- SGEMM: C = A(MxKd) @ B(KdxN) + bias ----------------
// 128x128 block tile, BK=8, 256 threads, 8x8 per thread.
// Requires M%128==0, N%128==0, Kd%8==0 (true for all our shapes).
__global__ void __launch_bounds__(256)
gemm_bias(const float* __restrict__ A, const float* __restrict__ B,
          const float* __restrict__ bias, float* __restrict__ C,
          int M, int N, int Kd)
{
    __shared__ float As[8][128];
    __shared__ float Bs[8][128];

    const int tid = threadIdx.x;
    const int tx  = tid & 15;        // 0..15
    const int ty  = tid >> 4;        // 0..15
    const int brow = blockIdx.y * 128;
    const int bcol = blockIdx.x * 128;

    float acc[8][8];
    #pragma unroll
    for (int i = 0; i < 8; i++)
        #pragma unroll
        for (int j = 0; j < 8; j++) acc[i][j] = 0.f;

    const int arow   = tid >> 1;        // 0..127
    const int acol   = (tid & 1) * 4;   // 0 or 4
    const int brow_l = tid >> 5;        // 0..7
    const int bcol_l = (tid & 31) * 4;  // 0..124

    for (int k0 = 0; k0 < Kd; k0 += 8) {
        float4 av = *(const float4*)(A + (size_t)(brow + arow) * Kd + k0 + acol);
        As[acol + 0][arow] = av.x;
        As[acol + 1][arow] = av.y;
        As[acol + 2][arow] = av.z;
        As[acol + 3][arow] = av.w;
        float4 bv = *(const float4*)(B + (size_t)(k0 + brow_l) * N + bcol + bcol_l);
        *(float4*)&Bs[brow_l][bcol_l] = bv;
        __syncthreads();

        #pragma unroll
        for (int kk = 0; kk < 8; kk++) {
            float ra[8], rb[8];
            #pragma unroll
            for (int i = 0; i < 8; i++) ra[i] = As[kk][ty * 8 + i];
            #pragma unroll
            for (int j = 0; j < 8; j++) rb[j] = Bs[kk][tx * 8 + j];
            #pragma unroll
            for (int i = 0; i < 8; i++)
                #pragma unroll
                for (int j = 0; j < 8; j++)
                    acc[i][j] = fmaf(ra[i], rb[j], acc[i][j]);
        }
        __syncthreads();
    }

    #pragma unroll
    for (int i = 0; i < 8; i++) {
        const int r = brow + ty * 8 + i;
        #pragma unroll
        for (int j = 0; j < 8; j += 4) {
            const int c = bcol + tx * 8 + j;
            float4 o;
            o.x = acc[i][j + 0] + bias[c + 0];
            o.y = acc[i][j + 1] + bias[c + 1];
            o.z = acc[i][j + 2] + bias[c + 2];
            o.w = acc[i][j + 3] + bias[c + 3];
            *(float4*)(C + (size_t)r * N + c) = o;
        }
    }
}

// ---------------- softmax over 16 (scales*k) per (row, head), in place ----------------
__global__ void softmax16_kernel()
{
    int idx = blockIdx.x * blockDim.x + threadIdx.x;
    if (idx >= NROWS * NHEADS) return;
    int r  = idx >> 3;
    int hd = idx & 7;
    float* a = g_attn + (size_t)r * 128 + hd * 16;
    float mx = -1e30f;
    #pragma unroll
    for (int j = 0; j < 16; j++) mx = fmaxf(mx, a[j]);
    float e[16];
    float sum = 0.f;
    #pragma unroll
    for (int j = 0; j < 16; j++) { e[j] = expf(a[j] - mx); sum += e[j]; }
    float inv = 1.f / sum;
    #pragma unroll
    for (int j = 0; j < 16; j++) a[j] = e[j] * inv;
}

// ---------------- bilinear sampling + attention-weighted reduce ----------------
// one warp per (b, head, pixel); lane = channel d (DK == 32)
__global__ void __launch_bounds__(256)
sample_kernel(const float* __restrict__ refp)
{
    const int gw   = blockIdx.x * (blockDim.x >> 5) + (threadIdx.x >> 5);
    const int lane = threadIdx.x & 31;
    if (gw >= 32 * NPIX) return;     // 32 = B*HEADS

    const int n    = gw >> 12;       // b*8+head
    const int pix  = gw & (NPIX - 1);
    const int b    = n >> 3;
    const int head = n & 7;
    const int row  = b * NPIX + pix; // q-row index

    const float rx = refp[pix * 2 + 0];
    const float ry = refp[pix * 2 + 1];

    const int   dims[4]   = {16, 32, 64, 128};
    const int   rowoff[4] = {0, 1024, 5120, 21504};

    float acc = 0.f;

    #pragma unroll
    for (int s = 0; s < 4; s++) {
        const int hl = dims[s], wl = dims[s];
        const float* kfb = g_kf + ((size_t)(rowoff[s] + b * hl * wl)) * CMODEL
                         + head * DK + lane;
        const float refx = rx * (float)(wl - 1);
        const float refy = ry * (float)(hl - 1);
        const float invw = 1.f / (float)(wl - 1);
        const float invh = 1.f / (float)(hl - 1);

        #pragma unroll
        for (int k = 0; k < 4; k++) {
            const int oc = (((head * 4 + s) * 4 + k)) * 2;
            const float px = refx + g_off[(size_t)row * CMODEL + oc + 0];
            const float py = refy + g_off[(size_t)row * CMODEL + oc + 1];
            // normalized grid then un-normalize (faithful to reference)
            const float gxn = 2.f * px * invw - 1.f;
            const float gyn = 2.f * py * invh - 1.f;
            const float ix = ((gxn + 1.f) * (float)wl - 1.f) * 0.5f;
            const float iy = ((gyn + 1.f) * (float)hl - 1.f) * 0.5f;
            const float x0 = floorf(ix), y0 = floorf(iy);
            const float wx1 = ix - x0, wx0 = 1.f - wx1;
            const float wy1 = iy - y0, wy0 = 1.f - wy1;

            const float Aw = g_attn[(size_t)row * 128 + head * 16 + s * 4 + k];

            float sv = 0.f;
            #pragma unroll
            for (int t = 0; t < 4; t++) {
                const float xx = x0 + (float)(t & 1);
                const float yy = y0 + (float)(t >> 1);
                const float wt = ((t & 1) ? wx1 : wx0) * ((t >> 1) ? wy1 : wy0);
                const bool m = (xx >= 0.f) && (xx <= (float)(wl - 1)) &&
                               (yy >= 0.f) && (yy <= (float)(hl - 1));
                const int xc = (int)fminf(fmaxf(xx, 0.f), (float)(wl - 1));
                const int yc = (int)fminf(fmaxf(yy, 0.f), (float)(hl - 1));
                const float v = kfb[(size_t)(yc * wl + xc) * CMODEL];
                sv += m ? (wt * v) : 0.f;
            }
            acc += Aw * sv;
        }
    }
    // raw-view layout: flat == row-major (B*HW, 256) for the final GEMM
    g_feat[((size_t)n * NPIX + pix) * DK + lane] = acc;
}

// ---------------- host launcher ----------------
extern "C" void kernel_launch(void* const* d_in, const int* in_sizes, int n_in,
                              void* d_out, int out_size)
{
    // identify inputs by element count (order-robust; within-size-class order
    // is Wq,Wk,Woff,Wm / bq,bk,boff,bm in both plausible metadata orders)
    const float* query = nullptr;
    const float* keys[4] = {nullptr, nullptr, nullptr, nullptr};
    const float* refp = nullptr;
    const float* Wmats[4] = {nullptr, nullptr, nullptr, nullptr};
    const float* bvecs[4] = {nullptr, nullptr, nullptr, nullptr};
    const float* WA = nullptr;
    const float* bA = nullptr;
    int wc = 0, bc = 0;
    bool qseen = false;

    for (int i = 0; i < n_in; i++) {
        const float* p = (const float*)d_in[i];
        switch (in_sizes[i]) {
            case 4194304:  if (!qseen) { query = p; qseen = true; } else keys[2] = p; break;
            case 262144:   keys[0] = p; break;
            case 1048576:  keys[1] = p; break;
            case 16777216: keys[3] = p; break;
            case 8192:     refp = p; break;
            case 32768:    WA = p; break;
            case 128:      bA = p; break;
            case 65536:    if (wc < 4) Wmats[wc++] = p; break;
            case 256:      if (bc < 4) bvecs[bc++] = p; break;
            default: break;
        }
    }
    const float* Wq = Wmats[0]; const float* bq = bvecs[0];
    const float* Wk = Wmats[1]; const float* bk = bvecs[1];
    const float* Woff = Wmats[2]; const float* boff = bvecs[2];
    const float* Wm = Wmats[3]; const float* bm = bvecs[3];

    float *qb, *ob, *ab, *kb, *fb;
    cudaGetSymbolAddress((void**)&qb, g_q);
    cudaGetSymbolAddress((void**)&ob, g_off);
    cudaGetSymbolAddress((void**)&ab, g_attn);
    cudaGetSymbolAddress((void**)&kb, g_kf);
    cudaGetSymbolAddress((void**)&fb, g_feat);

    // 1) q projection
    gemm_bias<<<dim3(2, 128), 256>>>(query, Wq, bq, qb, NROWS, 256, 256);
    // 2) offsets + attention logits
    gemm_bias<<<dim3(2, 128), 256>>>(qb, Woff, boff, ob, NROWS, 256, 256);
    gemm_bias<<<dim3(1, 128), 256>>>(qb, WA, bA, ab, NROWS, 128, 256);
    // 3) softmax over scales*k per head
    softmax16_kernel<<<(NROWS * NHEADS + 255) / 256, 256>>>();
    // 4) key projections (row offsets 0,1024,5120,21504)
    gemm_bias<<<dim3(2, 8),   256>>>(keys[0], Wk, bk, kb + (size_t)0     * 256, 1024,  256, 256);
    gemm_bias<<<dim3(2, 32),  256>>>(keys[1], Wk, bk, kb + (size_t)1024  * 256, 4096,  256, 256);
    gemm_bias<<<dim3(2, 128), 256>>>(keys[2], Wk, bk, kb + (size_t)5120  * 256, 16384, 256, 256);
    gemm_bias<<<dim3(2, 512), 256>>>(keys[3], Wk, bk, kb + (size_t)21504 * 256, 65536, 256, 256);
    // 5) sampling + weighted reduction (one warp per (b,head,pixel))
    sample_kernel<<<(32 * NPIX) / 8, 256>>>(refp);
    // 6) output projection
    gemm_bias<<<dim3(2, 128), 256>>>(fb, Wm, bm, (float*)d_out, NROWS, 256, 256);
}

// round 3
// speedup vs baseline: 1.5369x; 1.5369x over previous
#include <cuda_runtime.h>
#include <cuda_bf16.h>
#include <cstdint>

typedef __nv_bfloat16 bf16;

// ---------------- problem constants ----------------
#define NHEADS  8
#define NPIX    4096
#define NROWS   16384           // B * H * W
#define KF_ROWS 87040           // key pyramid rows total

// ---------------- scratch (device globals; allocation-free) ----------------
__device__ bf16  g_xh[(size_t)NROWS * 256];     // query split hi
__device__ bf16  g_xl[(size_t)NROWS * 256];     // query split lo
__device__ bf16  g_qh[(size_t)NROWS * 256];     // q = xWq+b, split hi
__device__ bf16  g_ql[(size_t)NROWS * 256];
__device__ float g_off [(size_t)NROWS * 256];
__device__ float g_attn[(size_t)NROWS * 128];
__device__ bf16  g_kh[(size_t)KF_ROWS * 256];   // keys split hi
__device__ bf16  g_kl[(size_t)KF_ROWS * 256];
__device__ float g_kf[(size_t)KF_ROWS * 256];   // projected keys fp32
__device__ bf16  g_fh[(size_t)NROWS * 256];     // sampled feat split hi
__device__ bf16  g_fl[(size_t)NROWS * 256];
__device__ bf16  g_wth[5 * 65536];              // transposed weights hi (Wq,Wk,Woff,WA,Wm)
__device__ bf16  g_wtl[5 * 65536];

// ---------------- tiny PTX helpers ----------------
static __device__ __forceinline__ uint32_t smem_u32(const void* p) {
    uint32_t a;
    asm("{ .reg .u64 t; cvta.to.shared.u64 t, %1; cvt.u32.u64 %0, t; }" : "=r"(a) : "l"(p));
    return a;
}
static __device__ __forceinline__ void cp16(uint32_t s, const void* g) {
    asm volatile("cp.async.cg.shared.global [%0], [%1], 16;" :: "r"(s), "l"(g));
}
static __device__ __forceinline__ void cp_commit() { asm volatile("cp.async.commit_group;"); }
static __device__ __forceinline__ void cp_wait1()  { asm volatile("cp.async.wait_group 1;"); }
static __device__ __forceinline__ void cp_wait0()  { asm volatile("cp.async.wait_group 0;"); }

static __device__ __forceinline__ void ldm_x4(uint32_t* r, uint32_t addr) {
    asm volatile("ldmatrix.sync.aligned.m8n8.x4.shared.b16 {%0,%1,%2,%3}, [%4];"
                 : "=r"(r[0]), "=r"(r[1]), "=r"(r[2]), "=r"(r[3]) : "r"(addr));
}
static __device__ __forceinline__ void mma16816(float* c, const uint32_t* a, const uint32_t* b) {
    asm volatile("mma.sync.aligned.m16n8k16.row.col.f32.bf16.bf16.f32 "
                 "{%0,%1,%2,%3}, {%4,%5,%6,%7}, {%8,%9}, {%0,%1,%2,%3};"
                 : "+f"(c[0]), "+f"(c[1]), "+f"(c[2]), "+f"(c[3])
                 : "r"(a[0]), "r"(a[1]), "r"(a[2]), "r"(a[3]), "r"(b[0]), "r"(b[1]));
}

static __device__ __forceinline__ uint32_t packbf(bf16 a, bf16 b) {
    __nv_bfloat162 t(a, b);
    return *reinterpret_cast<uint32_t*>(&t);
}

// ---------------- split / transpose kernels ----------------
__global__ void split_kernel(const float* __restrict__ src, bf16* __restrict__ hi,
                             bf16* __restrict__ lo, int n4) {
    int i = blockIdx.x * blockDim.x + threadIdx.x;
    if (i >= n4) return;
    float4 v = ((const float4*)src)[i];
    bf16 h0 = __float2bfloat16(v.x); float l0 = v.x - __bfloat162float(h0);
    bf16 h1 = __float2bfloat16(v.y); float l1 = v.y - __bfloat162float(h1);
    bf16 h2 = __float2bfloat16(v.z); float l2 = v.z - __bfloat162float(h2);
    bf16 h3 = __float2bfloat16(v.w); float l3 = v.w - __bfloat162float(h3);
    uint2 H; H.x = packbf(h0, h1); H.y = packbf(h2, h3);
    uint2 L; L.x = packbf(__float2bfloat16(l0), __float2bfloat16(l1));
    L.y = packbf(__float2bfloat16(l2), __float2bfloat16(l3));
    ((uint2*)hi)[i] = H;
    ((uint2*)lo)[i] = L;
}

// W (256 x N) row-major -> T (N x 256) split
__global__ void wtrans_kernel(const float* __restrict__ W, bf16* __restrict__ Th,
                              bf16* __restrict__ Tl, int N) {
    int idx = blockIdx.x * blockDim.x + threadIdx.x;
    if (idx >= N * 256) return;
    int k = idx & 255, n = idx >> 8;
    float v = W[(size_t)k * N + n];
    bf16 h = __float2bfloat16(v);
    Th[idx] = h;
    Tl[idx] = __float2bfloat16(v - __bfloat162float(h));
}

// ---------------- bf16x3 mma.sync GEMM ----------------
// C(M x N) = A(M x 256) @ B(256 x N) + bias,  D = Ah*Bh + Al*Bh + Ah*Bl.
// A: (Ah, Al) [M,256] bf16 row-major.  B: (Bh, Bl) given as W^T [N,256] bf16 row-major
// (= column-major B, matching mma .row.col).  CTA tile 128x128, warp tile 64x32, BK=32.
#define APAD 40              // row stride in bf16 elems (80 B -> conflict-free ldmatrix)

__global__ void __launch_bounds__(256)
gemm3p(const bf16* __restrict__ Ah, const bf16* __restrict__ Al,
       const bf16* __restrict__ Bh, const bf16* __restrict__ Bl,
       const float* __restrict__ bias,
       float* __restrict__ Cf, bf16* __restrict__ Ch, bf16* __restrict__ Cl, int N)
{
    __shared__ bf16 sA[2][128 * APAD];
    __shared__ bf16 sB[2][128 * APAD];

    const int tid   = threadIdx.x;
    const int lane  = tid & 31;
    const int wid   = tid >> 5;
    const int warpM = wid >> 2;          // 0..1
    const int warpN = wid & 3;           // 0..3
    const int brow  = blockIdx.y * 128;
    const int bcol  = blockIdx.x * 128;

    float acc[4][4][4];
    #pragma unroll
    for (int i = 0; i < 4; i++)
        #pragma unroll
        for (int j = 0; j < 4; j++)
            #pragma unroll
            for (int q = 0; q < 4; q++) acc[i][j][q] = 0.f;

    const uint32_t sa[2] = { smem_u32(sA[0]), smem_u32(sA[1]) };
    const uint32_t sbm[2] = { smem_u32(sB[0]), smem_u32(sB[1]) };

    // cp.async thread mapping: 512 16B-chunks per tile, 2 per thread
    const int ldr = tid >> 2;            // 0..63 base row
    const int ldq = tid & 3;             // quarter within row

    // ldmatrix per-lane offsets
    const int rrA = ((lane >> 3) & 1) * 8 + (lane & 7);
    const int ccA = (lane >> 4) * 8;
    const int rrB = (lane >> 4) * 8 + (lane & 7);
    const int ccB = ((lane >> 3) & 1) * 8;

    // virtual iteration: it in [0,24), seg = it>>3, k0 = (it&7)*32
    #define LOADTILE(stage, it_) do {                                              \
        const int seg_ = (it_) >> 3;                                               \
        const int k0_  = ((it_) & 7) * 32;                                         \
        const bf16* As_ = (seg_ == 1) ? Al : Ah;                                   \
        const bf16* Bs_ = (seg_ == 2) ? Bl : Bh;                                   \
        _Pragma("unroll")                                                          \
        for (int i_ = 0; i_ < 2; i_++) {                                           \
            const int r_ = ldr + i_ * 64;                                          \
            cp16(sa[stage] + (uint32_t)(r_ * APAD + ldq * 8) * 2,                  \
                 As_ + (size_t)(brow + r_) * 256 + k0_ + ldq * 8);                 \
            cp16(sbm[stage] + (uint32_t)(r_ * APAD + ldq * 8) * 2,                 \
                 Bs_ + (size_t)(bcol + r_) * 256 + k0_ + ldq * 8);                 \
        }                                                                          \
        cp_commit();                                                               \
    } while (0)

    LOADTILE(0, 0);

    #pragma unroll 1
    for (int it = 0; it < 24; ++it) {
        const int stage = it & 1;
        if (it + 1 < 24) {
            LOADTILE(stage ^ 1, it + 1);
            cp_wait1();
        } else {
            cp_wait0();
        }
        __syncthreads();

        const uint32_t A0 = sa[stage]  + (uint32_t)((warpM * 64 + rrA) * APAD + ccA) * 2;
        const uint32_t B0 = sbm[stage] + (uint32_t)((warpN * 32 + rrB) * APAD + ccB) * 2;

        #pragma unroll
        for (int k2 = 0; k2 < 2; k2++) {
            uint32_t afr[4][4];
            #pragma unroll
            for (int mi = 0; mi < 4; mi++)
                ldm_x4(afr[mi], A0 + (uint32_t)(mi * 16 * APAD + k2 * 16) * 2);
            uint32_t bfr[4][2];
            #pragma unroll
            for (int np = 0; np < 2; np++) {
                uint32_t t[4];
                ldm_x4(t, B0 + (uint32_t)(np * 16 * APAD + k2 * 16) * 2);
                bfr[np * 2 + 0][0] = t[0]; bfr[np * 2 + 0][1] = t[1];
                bfr[np * 2 + 1][0] = t[2]; bfr[np * 2 + 1][1] = t[3];
            }
            #pragma unroll
            for (int mi = 0; mi < 4; mi++)
                #pragma unroll
                for (int nf = 0; nf < 4; nf++)
                    mma16816(acc[mi][nf], afr[mi], bfr[nf]);
        }
        __syncthreads();
    }

    // ---- epilogue ----
    const int g  = lane >> 2;
    const int tg = lane & 3;
    #pragma unroll
    for (int mi = 0; mi < 4; mi++) {
        #pragma unroll
        for (int nf = 0; nf < 4; nf++) {
            const int row = brow + warpM * 64 + mi * 16 + g;
            const int col = bcol + warpN * 32 + nf * 8 + tg * 2;
            const float b0 = bias[col], b1 = bias[col + 1];
            const float v0 = acc[mi][nf][0] + b0, v1 = acc[mi][nf][1] + b1;
            const float v2 = acc[mi][nf][2] + b0, v3 = acc[mi][nf][3] + b1;
            if (Cf) {
                *(float2*)(Cf + (size_t)row * N + col)       = make_float2(v0, v1);
                *(float2*)(Cf + (size_t)(row + 8) * N + col) = make_float2(v2, v3);
            } else {
                bf16 h0 = __float2bfloat16(v0), h1 = __float2bfloat16(v1);
                bf16 h2 = __float2bfloat16(v2), h3 = __float2bfloat16(v3);
                *(uint32_t*)(Ch + (size_t)row * N + col)       = packbf(h0, h1);
                *(uint32_t*)(Ch + (size_t)(row + 8) * N + col) = packbf(h2, h3);
                *(uint32_t*)(Cl + (size_t)row * N + col) =
                    packbf(__float2bfloat16(v0 - __bfloat162float(h0)),
                           __float2bfloat16(v1 - __bfloat162float(h1)));
                *(uint32_t*)(Cl + (size_t)(row + 8) * N + col) =
                    packbf(__float2bfloat16(v2 - __bfloat162float(h2)),
                           __float2bfloat16(v3 - __bfloat162float(h3)));
            }
        }
    }
}

// ---------------- softmax over 16 (scales*k) per (row, head), in place ----------------
__global__ void softmax16_kernel()
{
    int idx = blockIdx.x * blockDim.x + threadIdx.x;
    if (idx >= NROWS * NHEADS) return;
    int r  = idx >> 3;
    int hd = idx & 7;
    float* a = g_attn + (size_t)r * 128 + hd * 16;
    float mx = -1e30f;
    #pragma unroll
    for (int j = 0; j < 16; j++) mx = fmaxf(mx, a[j]);
    float e[16];
    float sum = 0.f;
    #pragma unroll
    for (int j = 0; j < 16; j++) { e[j] = expf(a[j] - mx); sum += e[j]; }
    float inv = 1.f / sum;
    #pragma unroll
    for (int j = 0; j < 16; j++) a[j] = e[j] * inv;
}

// ---------------- bilinear sampling + attention-weighted reduce ----------------
__global__ void __launch_bounds__(256)
sample_kernel(const float* __restrict__ refp)
{
    const int gw   = blockIdx.x * (blockDim.x >> 5) + (threadIdx.x >> 5);
    const int lane = threadIdx.x & 31;
    if (gw >= 32 * NPIX) return;

    const int n    = gw >> 12;        // b*8+head
    const int pix  = gw & (NPIX - 1);
    const int b    = n >> 3;
    const int head = n & 7;
    const int row  = b * NPIX + pix;

    const float rx = refp[pix * 2 + 0];
    const float ry = refp[pix * 2 + 1];

    const int dims[4]   = {16, 32, 64, 128};
    const int rowoff[4] = {0, 1024, 5120, 21504};

    float acc = 0.f;

    #pragma unroll
    for (int s = 0; s < 4; s++) {
        const int hl = dims[s], wl = dims[s];
        const float* kfb = g_kf + ((size_t)(rowoff[s] + b * hl * wl)) * 256
                         + head * 32 + lane;
        const float refx = rx * (float)(wl - 1);
        const float refy = ry * (float)(hl - 1);
        const float invw = 1.f / (float)(wl - 1);
        const float invh = 1.f / (float)(hl - 1);

        #pragma unroll
        for (int k = 0; k < 4; k++) {
            const int oc = (((head * 4 + s) * 4 + k)) * 2;
            const float px = refx + g_off[(size_t)row * 256 + oc + 0];
            const float py = refy + g_off[(size_t)row * 256 + oc + 1];
            const float gxn = 2.f * px * invw - 1.f;
            const float gyn = 2.f * py * invh - 1.f;
            const float ix = ((gxn + 1.f) * (float)wl - 1.f) * 0.5f;
            const float iy = ((gyn + 1.f) * (float)hl - 1.f) * 0.5f;
            const float x0 = floorf(ix), y0 = floorf(iy);
            const float wx1 = ix - x0, wx0 = 1.f - wx1;
            const float wy1 = iy - y0, wy0 = 1.f - wy1;

            const float Aw = g_attn[(size_t)row * 128 + head * 16 + s * 4 + k];

            float sv = 0.f;
            #pragma unroll
            for (int t = 0; t < 4; t++) {
                const float xx = x0 + (float)(t & 1);
                const float yy = y0 + (float)(t >> 1);
                const float wt = ((t & 1) ? wx1 : wx0) * ((t >> 1) ? wy1 : wy0);
                const bool m = (xx >= 0.f) && (xx <= (float)(wl - 1)) &&
                               (yy >= 0.f) && (yy <= (float)(hl - 1));
                const int xc = (int)fminf(fmaxf(xx, 0.f), (float)(wl - 1));
                const int yc = (int)fminf(fmaxf(yy, 0.f), (float)(hl - 1));
                const float v = kfb[(size_t)(yc * wl + xc) * 256];
                sv += m ? (wt * v) : 0.f;
            }
            acc += Aw * sv;
        }
    }
    const size_t oi = ((size_t)n * NPIX + pix) * 32 + lane;
    bf16 h = __float2bfloat16(acc);
    g_fh[oi] = h;
    g_fl[oi] = __float2bfloat16(acc - __bfloat162float(h));
}

// ---------------- host launcher ----------------
extern "C" void kernel_launch(void* const* d_in, const int* in_sizes, int n_in,
                              void* d_out, int out_size)
{
    const float* query = nullptr;
    const float* keys[4] = {nullptr, nullptr, nullptr, nullptr};
    const float* refp = nullptr;
    const float* Wmats[4] = {nullptr, nullptr, nullptr, nullptr};
    const float* bvecs[4] = {nullptr, nullptr, nullptr, nullptr};
    const float* WA = nullptr;
    const float* bA = nullptr;
    int wc = 0, bc = 0;
    bool qseen = false;

    for (int i = 0; i < n_in; i++) {
        const float* p = (const float*)d_in[i];
        switch (in_sizes[i]) {
            case 4194304:  if (!qseen) { query = p; qseen = true; } else keys[2] = p; break;
            case 262144:   keys[0] = p; break;
            case 1048576:  keys[1] = p; break;
            case 16777216: keys[3] = p; break;
            case 8192:     refp = p; break;
            case 32768:    WA = p; break;
            case 128:      bA = p; break;
            case 65536:    if (wc < 4) Wmats[wc++] = p; break;
            case 256:      if (bc < 4) bvecs[bc++] = p; break;
            default: break;
        }
    }
    const float* Wq = Wmats[0];   const float* bq = bvecs[0];
    const float* Wk = Wmats[1];   const float* bk = bvecs[1];
    const float* Woff = Wmats[2]; const float* boff = bvecs[2];
    const float* Wm = Wmats[3];   const float* bm = bvecs[3];

    bf16 *xh, *xl, *qh, *ql, *kh, *kl, *fh, *fl, *wth, *wtl;
    float *ob, *ab, *kfb;
    cudaGetSymbolAddress((void**)&xh, g_xh);   cudaGetSymbolAddress((void**)&xl, g_xl);
    cudaGetSymbolAddress((void**)&qh, g_qh);   cudaGetSymbolAddress((void**)&ql, g_ql);
    cudaGetSymbolAddress((void**)&kh, g_kh);   cudaGetSymbolAddress((void**)&kl, g_kl);
    cudaGetSymbolAddress((void**)&fh, g_fh);   cudaGetSymbolAddress((void**)&fl, g_fl);
    cudaGetSymbolAddress((void**)&wth, g_wth); cudaGetSymbolAddress((void**)&wtl, g_wtl);
    cudaGetSymbolAddress((void**)&ob, g_off);
    cudaGetSymbolAddress((void**)&ab, g_attn);
    cudaGetSymbolAddress((void**)&kfb, g_kf);

    // 1) splits: query + keys
    split_kernel<<<(4194304 / 4 + 255) / 256, 256>>>(query, xh, xl, 4194304 / 4);
    split_kernel<<<(262144 / 4 + 255) / 256, 256>>>(keys[0], kh + (size_t)0 * 256,     kl + (size_t)0 * 256,     262144 / 4);
    split_kernel<<<(1048576 / 4 + 255) / 256, 256>>>(keys[1], kh + (size_t)1024 * 256,  kl + (size_t)1024 * 256,  1048576 / 4);
    split_kernel<<<(4194304 / 4 + 255) / 256, 256>>>(keys[2], kh + (size_t)5120 * 256,  kl + (size_t)5120 * 256,  4194304 / 4);
    split_kernel<<<(16777216 / 4 + 255) / 256, 256>>>(keys[3], kh + (size_t)21504 * 256, kl + (size_t)21504 * 256, 16777216 / 4);

    // 2) transposed weight splits: slots 0=Wq 1=Wk 2=Woff 3=WA 4=Wm
    wtrans_kernel<<<(65536 + 255) / 256, 256>>>(Wq,   wth + 0 * 65536, wtl + 0 * 65536, 256);
    wtrans_kernel<<<(65536 + 255) / 256, 256>>>(Wk,   wth + 1 * 65536, wtl + 1 * 65536, 256);
    wtrans_kernel<<<(65536 + 255) / 256, 256>>>(Woff, wth + 2 * 65536, wtl + 2 * 65536, 256);
    wtrans_kernel<<<(32768 + 255) / 256, 256>>>(WA,   wth + 3 * 65536, wtl + 3 * 65536, 128);
    wtrans_kernel<<<(65536 + 255) / 256, 256>>>(Wm,   wth + 4 * 65536, wtl + 4 * 65536, 256);

    // 3) q projection (emit split bf16 directly)
    gemm3p<<<dim3(2, NROWS / 128), 256>>>(xh, xl, wth + 0 * 65536, wtl + 0 * 65536,
                                          bq, nullptr, qh, ql, 256);
    // 4) offsets + attention logits
    gemm3p<<<dim3(2, NROWS / 128), 256>>>(qh, ql, wth + 2 * 65536, wtl + 2 * 65536,
                                          boff, ob, nullptr, nullptr, 256);
    gemm3p<<<dim3(1, NROWS / 128), 256>>>(qh, ql, wth + 3 * 65536, wtl + 3 * 65536,
                                          bA, ab, nullptr, nullptr, 128);
    // 5) softmax
    softmax16_kernel<<<(NROWS * NHEADS + 255) / 256, 256>>>();
    // 6) key projection (single big GEMM over the whole pyramid)
    gemm3p<<<dim3(2, KF_ROWS / 128), 256>>>(kh, kl, wth + 1 * 65536, wtl + 1 * 65536,
                                            bk, kfb, nullptr, nullptr, 256);
    // 7) sampling (emits split bf16 feat)
    sample_kernel<<<(32 * NPIX) / 8, 256>>>(refp);
    // 8) output projection
    gemm3p<<<dim3(2, NROWS / 128), 256>>>(fh, fl, wth + 4 * 65536, wtl + 4 * 65536,
                                          bm, (float*)d_out, nullptr, nullptr, 256);
}